// round 11
// baseline (speedup 1.0000x reference)
#include <cuda_runtime.h>
#include <cuda_bf16.h>
#include <cstdint>

// Problem constants (fixed by reference)
#define NN 100000
#define EE 3200000
#define F_IN 512
#define HH 16
#define CC 7
#define CPAD 8

// GEMM1 tiling
#define GR 256
#define KT 16
#define NTILES (F_IN / KT)
#define XSS 20
#define GEMM_BLOCKS ((NN + GR - 1) / GR)     // 391
#define HIST_BLOCKS (EE / 4 / 256)           // 3125

// Edge chunking (atomic-contention reduction)
#define NCHUNK 16
#define CE (EE / NCHUNK)                     // 200000 (divisible by 4)

// Scan config
#define SB 512
#define NSB ((NN + SB - 1) / SB)             // 196

// Scratch (device globals). g_ccnt is zero at module load and re-zeroed at the
// END of each call (in k_gather2_fin), so every invocation starts from zeros.
__device__ int   g_ccnt[NCHUNK * NN];   // per-chunk in-degree
__device__ int   g_ccur[NCHUNK * NN];   // per-chunk permute cursors
__device__ int   g_rowptr[NN + 1];      // CSR row pointers (by dst)
__device__ int   g_bsum[NSB];
__device__ float g_dinv[NN];
__device__ int   g_csrc[EE];            // CSR src indices
__device__ float g_h1[NN * HH];         // x @ W1
__device__ float g_t2[NN * CPAD];       // relu(out1+b1) @ W2

#define CP_ASYNC16(smem_u32, gptr, valid)                                   \
    asm volatile("cp.async.cg.shared.global [%0], [%1], 16, %2;\n"          \
                 :: "r"(smem_u32), "l"(gptr), "r"((valid) ? 16 : 0))
#define CP_COMMIT() asm volatile("cp.async.commit_group;\n")
#define CP_WAIT(n)  asm volatile("cp.async.wait_group %0;\n" :: "n"(n))

// ---------------------------------------------------------------------------
// Combined launch: blocks [0, GEMM_BLOCKS) run gemm1 (h1 = x @ W1);
// blocks [GEMM_BLOCKS, +HIST_BLOCKS) run the chunked histogram (independent).
__global__ void __launch_bounds__(256, 4) k_gemm1_hist(const float* __restrict__ x,
                                                       const float* __restrict__ W1,
                                                       const int* __restrict__ dst) {
    __shared__ float xs[2][GR][XSS];
    __shared__ float ws[2][KT][HH];

    if (blockIdx.x >= GEMM_BLOCKS) {
        // ---- histogram part ----
        int base = ((blockIdx.x - GEMM_BLOCKS) * 256 + threadIdx.x) * 4;
        if (base < EE) {
            int c = base / CE;
            int* cnt = g_ccnt + c * NN;
            int4 d4 = *reinterpret_cast<const int4*>(dst + base);
            atomicAdd(&cnt[d4.x], 1);
            atomicAdd(&cnt[d4.y], 1);
            atomicAdd(&cnt[d4.z], 1);
            atomicAdd(&cnt[d4.w], 1);
        }
        return;
    }

    // ---- gemm part ----
    const int t = threadIdx.x;
    const int row0 = blockIdx.x * GR;
    const int rg = t >> 2;
    const int c0 = (t & 3) * 4;

    auto issue_tile = [&](int tile, int buf) {
        int k0 = tile * KT;
        #pragma unroll
        for (int j = 0; j < 4; j++) {
            int q = t + j * 256;
            int r = q >> 2;
            int cq = (q & 3) * 4;
            int grow = row0 + r;
            unsigned int sa = (unsigned int)__cvta_generic_to_shared(&xs[buf][r][cq]);
            CP_ASYNC16(sa, x + (size_t)grow * F_IN + k0 + cq, grow < NN);
        }
        if (t < 64) {
            int r = t >> 2;
            int cq = (t & 3) * 4;
            unsigned int sa = (unsigned int)__cvta_generic_to_shared(&ws[buf][r][cq]);
            CP_ASYNC16(sa, W1 + (size_t)(k0 + r) * HH + cq, 1);
        }
    };

    float acc[4][4] = {};

    issue_tile(0, 0);
    CP_COMMIT();

    #pragma unroll 4
    for (int it = 0; it < NTILES; it++) {
        int buf = it & 1;
        if (it + 1 < NTILES) {
            issue_tile(it + 1, buf ^ 1);
            CP_COMMIT();
            CP_WAIT(1);
        } else {
            CP_WAIT(0);
        }
        __syncthreads();

        #pragma unroll
        for (int kk = 0; kk < KT; kk++) {
            float4 w = *reinterpret_cast<const float4*>(&ws[buf][kk][c0]);
            #pragma unroll
            for (int i = 0; i < 4; i++) {
                float xv = xs[buf][rg + 64 * i][kk];
                acc[i][0] = fmaf(xv, w.x, acc[i][0]);
                acc[i][1] = fmaf(xv, w.y, acc[i][1]);
                acc[i][2] = fmaf(xv, w.z, acc[i][2]);
                acc[i][3] = fmaf(xv, w.w, acc[i][3]);
            }
        }
        __syncthreads();
    }

    #pragma unroll
    for (int i = 0; i < 4; i++) {
        int row = row0 + rg + 64 * i;
        if (row < NN) {
            float4 h = make_float4(acc[i][0], acc[i][1], acc[i][2], acc[i][3]);
            *reinterpret_cast<float4*>(g_h1 + (size_t)row * HH + c0) = h;
        }
    }
}

// ---------------------------------------------------------------------------
// Block-local exclusive scan of total per-node counts + block sums
__global__ void __launch_bounds__(SB) k_scan1() {
    __shared__ int sh[SB];
    int t = threadIdx.x;
    int i = blockIdx.x * SB + t;
    int v = 0;
    if (i < NN) {
        #pragma unroll
        for (int c = 0; c < NCHUNK; c++) v += g_ccnt[c * NN + i];
    }
    sh[t] = v;
    __syncthreads();
    #pragma unroll
    for (int off = 1; off < SB; off <<= 1) {
        int add = (t >= off) ? sh[t - off] : 0;
        __syncthreads();
        sh[t] += add;
        __syncthreads();
    }
    if (i < NN) g_rowptr[i] = sh[t] - v;   // exclusive (local)
    if (t == SB - 1) g_bsum[blockIdx.x] = sh[SB - 1];
}

// Finalize rowptr, compute dinv, seed per-chunk cursors.
__global__ void __launch_bounds__(256) k_scan3() {
    __shared__ int sh[256];
    int t = threadIdx.x;
    int v = (t < NSB) ? g_bsum[t] : 0;
    sh[t] = v;
    __syncthreads();
    #pragma unroll
    for (int off = 1; off < 256; off <<= 1) {
        int add = (t >= off) ? sh[t - off] : 0;
        __syncthreads();
        sh[t] += add;
        __syncthreads();
    }
    int i = blockIdx.x * 256 + t;
    if (i < NN) {
        int blk = i / SB;
        int off = (blk == 0) ? 0 : sh[blk - 1];
        int rp = g_rowptr[i] + off;
        g_rowptr[i] = rp;
        int running = rp;
        #pragma unroll
        for (int c = 0; c < NCHUNK; c++) {
            g_ccur[c * NN + i] = running;
            running += g_ccnt[c * NN + i];
        }
        g_dinv[i] = rsqrtf((float)(running - rp) + 1.0f);
    }
    if (i == 0) g_rowptr[NN] = EE;
}

// Permute edges into CSR-by-dst via per-chunk cursors (contention / 16).
__global__ void k_permute(const int* __restrict__ src, const int* __restrict__ dst) {
    int base = (blockIdx.x * blockDim.x + threadIdx.x) * 4;
    if (base >= EE) return;
    int c = base / CE;
    int* cur = g_ccur + c * NN;
    int4 d4 = *reinterpret_cast<const int4*>(dst + base);
    int4 s4 = *reinterpret_cast<const int4*>(src + base);
    int p0 = atomicAdd(&cur[d4.x], 1);
    int p1 = atomicAdd(&cur[d4.y], 1);
    int p2 = atomicAdd(&cur[d4.z], 1);
    int p3 = atomicAdd(&cur[d4.w], 1);
    g_csrc[p0] = s4.x;
    g_csrc[p1] = s4.y;
    g_csrc[p2] = s4.z;
    g_csrc[p3] = s4.w;
}

// ---------------------------------------------------------------------------
// Fused: layer-1 CSR gather + relu + bias + (h2 @ W2) -> t2. 4 threads/node.
__global__ void __launch_bounds__(256) k_gather1_t2(const float* __restrict__ b1,
                                                    const float* __restrict__ W2) {
    __shared__ float w2s[HH][CPAD];
    __shared__ float b1s[HH];
    if (threadIdx.x < HH * CC) {
        int k = threadIdx.x / CC, c = threadIdx.x % CC;
        w2s[k][c] = W2[threadIdx.x];
    }
    if (threadIdx.x < HH) {
        b1s[threadIdx.x] = b1[threadIdx.x];
        w2s[threadIdx.x][CC] = 0.0f;
    }
    __syncthreads();

    int tid = blockIdx.x * blockDim.x + threadIdx.x;
    int iraw = tid >> 2;
    bool valid = iraw < NN;
    int i = valid ? iraw : NN - 1;   // clamp: keep warp converged for shfl
    int p = tid & 3;

    int beg = g_rowptr[i];
    int end = g_rowptr[i + 1];
    float di = g_dinv[i];

    float4 self = *reinterpret_cast<const float4*>(g_h1 + (size_t)i * HH + p * 4);
    float4 acc = make_float4(di * self.x, di * self.y, di * self.z, di * self.w);

    int j = beg;
    for (; j + 3 < end; j += 4) {
        int s0 = g_csrc[j];
        int s1 = g_csrc[j + 1];
        int s2 = g_csrc[j + 2];
        int s3 = g_csrc[j + 3];
        float w0 = g_dinv[s0], w1 = g_dinv[s1], w2 = g_dinv[s2], w3 = g_dinv[s3];
        float4 v0 = *reinterpret_cast<const float4*>(g_h1 + (size_t)s0 * HH + p * 4);
        float4 v1 = *reinterpret_cast<const float4*>(g_h1 + (size_t)s1 * HH + p * 4);
        float4 v2 = *reinterpret_cast<const float4*>(g_h1 + (size_t)s2 * HH + p * 4);
        float4 v3 = *reinterpret_cast<const float4*>(g_h1 + (size_t)s3 * HH + p * 4);
        acc.x = fmaf(w0, v0.x, acc.x); acc.y = fmaf(w0, v0.y, acc.y);
        acc.z = fmaf(w0, v0.z, acc.z); acc.w = fmaf(w0, v0.w, acc.w);
        acc.x = fmaf(w1, v1.x, acc.x); acc.y = fmaf(w1, v1.y, acc.y);
        acc.z = fmaf(w1, v1.z, acc.z); acc.w = fmaf(w1, v1.w, acc.w);
        acc.x = fmaf(w2, v2.x, acc.x); acc.y = fmaf(w2, v2.y, acc.y);
        acc.z = fmaf(w2, v2.z, acc.z); acc.w = fmaf(w2, v2.w, acc.w);
        acc.x = fmaf(w3, v3.x, acc.x); acc.y = fmaf(w3, v3.y, acc.y);
        acc.z = fmaf(w3, v3.z, acc.z); acc.w = fmaf(w3, v3.w, acc.w);
    }
    for (; j < end; j++) {
        int s0 = g_csrc[j];
        float w0 = g_dinv[s0];
        float4 v0 = *reinterpret_cast<const float4*>(g_h1 + (size_t)s0 * HH + p * 4);
        acc.x = fmaf(w0, v0.x, acc.x); acc.y = fmaf(w0, v0.y, acc.y);
        acc.z = fmaf(w0, v0.z, acc.z); acc.w = fmaf(w0, v0.w, acc.w);
    }

    // out1 slice + bias + relu (slice p covers k = 4p..4p+3)
    float4 hh;
    hh.x = fmaxf(di * acc.x + b1s[p * 4 + 0], 0.0f);
    hh.y = fmaxf(di * acc.y + b1s[p * 4 + 1], 0.0f);
    hh.z = fmaxf(di * acc.z + b1s[p * 4 + 2], 0.0f);
    hh.w = fmaxf(di * acc.w + b1s[p * 4 + 3], 0.0f);

    // butterfly: gather all 4 slices of this node into canonical order
    const unsigned FULL = 0xFFFFFFFFu;
    float4 o1;
    o1.x = __shfl_xor_sync(FULL, hh.x, 1);
    o1.y = __shfl_xor_sync(FULL, hh.y, 1);
    o1.z = __shfl_xor_sync(FULL, hh.z, 1);
    o1.w = __shfl_xor_sync(FULL, hh.w, 1);
    bool low1 = (p & 1) == 0;
    float4 a = low1 ? hh : o1;
    float4 b = low1 ? o1 : hh;

    float4 pa, pb;
    pa.x = __shfl_xor_sync(FULL, a.x, 2);
    pa.y = __shfl_xor_sync(FULL, a.y, 2);
    pa.z = __shfl_xor_sync(FULL, a.z, 2);
    pa.w = __shfl_xor_sync(FULL, a.w, 2);
    pb.x = __shfl_xor_sync(FULL, b.x, 2);
    pb.y = __shfl_xor_sync(FULL, b.y, 2);
    pb.z = __shfl_xor_sync(FULL, b.z, 2);
    pb.w = __shfl_xor_sync(FULL, b.w, 2);
    bool low2 = (p & 2) == 0;
    float4 s0 = low2 ? a : pa;
    float4 s1 = low2 ? b : pb;
    float4 s2 = low2 ? pa : a;
    float4 s3 = low2 ? pb : b;

    float h[HH] = { s0.x, s0.y, s0.z, s0.w, s1.x, s1.y, s1.z, s1.w,
                    s2.x, s2.y, s2.z, s2.w, s3.x, s3.y, s3.z, s3.w };

    int c0 = p * 2;
    float r0 = 0.0f, r1 = 0.0f;
    #pragma unroll
    for (int k = 0; k < HH; k++) {
        r0 = fmaf(h[k], w2s[k][c0], r0);
        r1 = fmaf(h[k], w2s[k][c0 + 1], r1);
    }
    if (valid) {
        float2 r = make_float2(r0, r1);
        *reinterpret_cast<float2*>(g_t2 + (size_t)i * CPAD + c0) = r;
    }
}

// ---------------------------------------------------------------------------
// Layer-2 aggregation + bias + log_softmax, fused. 2 threads per node.
// Also re-zeroes g_ccnt for the next invocation.
__global__ void __launch_bounds__(256) k_gather2_fin(const float* __restrict__ b2,
                                                     float* __restrict__ out) {
    int tid = blockIdx.x * blockDim.x + threadIdx.x;
    // reset chunk counters (grid covers 2*NN = 200K threads; 8 ints each = 1.6M)
    {
        int z = tid * 8;
        if (z < NCHUNK * NN) {
            int4 zero = make_int4(0, 0, 0, 0);
            *reinterpret_cast<int4*>(g_ccnt + z) = zero;
            *reinterpret_cast<int4*>(g_ccnt + z + 4) = zero;
        }
    }

    int iraw = tid >> 1;
    bool valid = iraw < NN;
    int i = valid ? iraw : NN - 1;   // clamp: keep full warp for shfl
    int p = tid & 1;

    int beg = g_rowptr[i];
    int end = g_rowptr[i + 1];
    float di = g_dinv[i];

    float4 self = *reinterpret_cast<const float4*>(g_t2 + (size_t)i * CPAD + p * 4);
    float4 acc = make_float4(di * self.x, di * self.y, di * self.z, di * self.w);

    int j = beg;
    for (; j + 3 < end; j += 4) {
        int s0 = g_csrc[j];
        int s1 = g_csrc[j + 1];
        int s2 = g_csrc[j + 2];
        int s3 = g_csrc[j + 3];
        float w0 = g_dinv[s0], w1 = g_dinv[s1], w2 = g_dinv[s2], w3 = g_dinv[s3];
        float4 v0 = *reinterpret_cast<const float4*>(g_t2 + (size_t)s0 * CPAD + p * 4);
        float4 v1 = *reinterpret_cast<const float4*>(g_t2 + (size_t)s1 * CPAD + p * 4);
        float4 v2 = *reinterpret_cast<const float4*>(g_t2 + (size_t)s2 * CPAD + p * 4);
        float4 v3 = *reinterpret_cast<const float4*>(g_t2 + (size_t)s3 * CPAD + p * 4);
        acc.x = fmaf(w0, v0.x, acc.x); acc.y = fmaf(w0, v0.y, acc.y);
        acc.z = fmaf(w0, v0.z, acc.z); acc.w = fmaf(w0, v0.w, acc.w);
        acc.x = fmaf(w1, v1.x, acc.x); acc.y = fmaf(w1, v1.y, acc.y);
        acc.z = fmaf(w1, v1.z, acc.z); acc.w = fmaf(w1, v1.w, acc.w);
        acc.x = fmaf(w2, v2.x, acc.x); acc.y = fmaf(w2, v2.y, acc.y);
        acc.z = fmaf(w2, v2.z, acc.z); acc.w = fmaf(w2, v2.w, acc.w);
        acc.x = fmaf(w3, v3.x, acc.x); acc.y = fmaf(w3, v3.y, acc.y);
        acc.z = fmaf(w3, v3.z, acc.z); acc.w = fmaf(w3, v3.w, acc.w);
    }
    for (; j < end; j++) {
        int s0 = g_csrc[j];
        float w0 = g_dinv[s0];
        float4 v0 = *reinterpret_cast<const float4*>(g_t2 + (size_t)s0 * CPAD + p * 4);
        acc.x = fmaf(w0, v0.x, acc.x); acc.y = fmaf(w0, v0.y, acc.y);
        acc.z = fmaf(w0, v0.z, acc.z); acc.w = fmaf(w0, v0.w, acc.w);
    }

    // logits for this thread's 4 class slots (slot 7 = padding -> -inf)
    float val[4];
    val[0] = di * acc.x; val[1] = di * acc.y; val[2] = di * acc.z; val[3] = di * acc.w;
    #pragma unroll
    for (int k = 0; k < 4; k++) {
        int c = p * 4 + k;
        val[k] = (c < CC) ? val[k] + b2[c] : -1e30f;
    }

    float m4 = fmaxf(fmaxf(val[0], val[1]), fmaxf(val[2], val[3]));
    float mo = __shfl_xor_sync(0xFFFFFFFFu, m4, 1);
    float m = fmaxf(m4, mo);

    float s4 = __expf(val[0] - m) + __expf(val[1] - m) +
               __expf(val[2] - m) + __expf(val[3] - m);
    float so = __shfl_xor_sync(0xFFFFFFFFu, s4, 1);
    float lse = m + __logf(s4 + so);

    if (valid) {
        #pragma unroll
        for (int k = 0; k < 4; k++) {
            int c = p * 4 + k;
            if (c < CC) out[(size_t)i * CC + c] = val[k] - lse;
        }
    }
}

// ---------------------------------------------------------------------------
extern "C" void kernel_launch(void* const* d_in, const int* in_sizes, int n_in,
                              void* d_out, int out_size) {
    const float* x    = (const float*)d_in[0];
    const int* eidx   = (const int*)d_in[1];
    const float* W1   = (const float*)d_in[2];
    const float* b1   = (const float*)d_in[3];
    const float* W2   = (const float*)d_in[4];
    const float* b2   = (const float*)d_in[5];
    float* out        = (float*)d_out;

    const int* src = eidx;        // edge_index[0]
    const int* dst = eidx + EE;   // edge_index[1]

    const int TB = 256;
    k_gemm1_hist<<<GEMM_BLOCKS + HIST_BLOCKS, TB>>>(x, W1, dst);
    k_scan1<<<NSB, SB>>>();
    k_scan3<<<(NN + 255) / 256, 256>>>();
    k_permute<<<HIST_BLOCKS, TB>>>(src, dst);
    k_gather1_t2<<<(NN * 4 + TB - 1) / TB, TB>>>(b1, W2);
    k_gather2_fin<<<(NN * 2 + TB - 1) / TB, TB>>>(b2, out);
}

// round 12
// speedup vs baseline: 1.1582x; 1.1582x over previous
#include <cuda_runtime.h>
#include <cuda_bf16.h>
#include <cstdint>

// Problem constants (fixed by reference)
#define NN 100000
#define EE 3200000
#define F_IN 512
#define HH 16
#define CC 7
#define CPAD 8

// GEMM1 tiling
#define GR 256
#define KT 16
#define NTILES (F_IN / KT)
#define XSS 20
#define GEMM_BLOCKS ((NN + GR - 1) / GR)     // 391
#define EDGE_BLOCKS (EE / 4 / 256)           // 3125

// Scan config
#define SB 512
#define NSB ((NN + SB - 1) / SB)             // 196

// Scratch (device globals). g_cnt is zero at module load and re-zeroed at the
// END of each call (in k_gather2_fin), so every invocation starts from zeros.
__device__ int   g_cnt[NN];        // in-degree (excl self loop)
__device__ int   g_cursor[NN];     // permute cursors (seeded = rowptr)
__device__ int   g_rowptr[NN + 1]; // CSR row pointers (by dst)
__device__ int   g_bsum[NSB];
__device__ float g_dinv[NN];
__device__ int   g_csrc[EE];       // CSR src indices
__device__ float g_h1[NN * HH];    // x @ W1
__device__ float g_t2[NN * CPAD];  // relu(out1+b1) @ W2

#define CP_ASYNC16(smem_u32, gptr, valid)                                   \
    asm volatile("cp.async.cg.shared.global [%0], [%1], 16, %2;\n"          \
                 :: "r"(smem_u32), "l"(gptr), "r"((valid) ? 16 : 0))
#define CP_COMMIT() asm volatile("cp.async.commit_group;\n")
#define CP_WAIT(n)  asm volatile("cp.async.wait_group %0;\n" :: "n"(n))

// ---------------------------------------------------------------------------
// Histogram: 4 edges per thread (int4).
__global__ void k_hist(const int* __restrict__ dst) {
    int base = (blockIdx.x * blockDim.x + threadIdx.x) * 4;
    if (base >= EE) return;
    int4 d4 = *reinterpret_cast<const int4*>(dst + base);
    atomicAdd(&g_cnt[d4.x], 1);
    atomicAdd(&g_cnt[d4.y], 1);
    atomicAdd(&g_cnt[d4.z], 1);
    atomicAdd(&g_cnt[d4.w], 1);
}

// Block-local exclusive scan (Hillis-Steele) + block sums
__global__ void __launch_bounds__(SB) k_scan1() {
    __shared__ int sh[SB];
    int t = threadIdx.x;
    int i = blockIdx.x * SB + t;
    int v = (i < NN) ? g_cnt[i] : 0;
    sh[t] = v;
    __syncthreads();
    #pragma unroll
    for (int off = 1; off < SB; off <<= 1) {
        int add = (t >= off) ? sh[t - off] : 0;
        __syncthreads();
        sh[t] += add;
        __syncthreads();
    }
    if (i < NN) g_rowptr[i] = sh[t] - v;   // exclusive (local)
    if (t == SB - 1) g_bsum[blockIdx.x] = sh[SB - 1];
}

// Finalize rowptr (each block redundantly scans the 196 block sums), compute
// dinv, seed permute cursor.
__global__ void __launch_bounds__(256) k_scan3() {
    __shared__ int sh[256];
    int t = threadIdx.x;
    int v = (t < NSB) ? g_bsum[t] : 0;
    sh[t] = v;
    __syncthreads();
    #pragma unroll
    for (int off = 1; off < 256; off <<= 1) {
        int add = (t >= off) ? sh[t - off] : 0;
        __syncthreads();
        sh[t] += add;
        __syncthreads();
    }
    int i = blockIdx.x * 256 + t;
    if (i < NN) {
        int blk = i / SB;
        int off = (blk == 0) ? 0 : sh[blk - 1];
        int rp = g_rowptr[i] + off;
        g_rowptr[i] = rp;
        g_cursor[i] = rp;
        g_dinv[i] = rsqrtf((float)g_cnt[i] + 1.0f);
    }
    if (i == 0) g_rowptr[NN] = EE;
}

// ---------------------------------------------------------------------------
// Fused launch: blocks [0, GEMM_BLOCKS) run gemm1 (FMA/HBM-bound);
// blocks [GEMM_BLOCKS, +EDGE_BLOCKS) run the CSR permute (L2-scatter-bound).
// The two are independent and resource-complementary -> permute hides under gemm.
__global__ void __launch_bounds__(256, 4) k_gemm1_permute(const float* __restrict__ x,
                                                          const float* __restrict__ W1,
                                                          const int* __restrict__ src,
                                                          const int* __restrict__ dst) {
    __shared__ float xs[2][GR][XSS];
    __shared__ float ws[2][KT][HH];

    if (blockIdx.x >= GEMM_BLOCKS) {
        // ---- permute part ----
        int base = ((blockIdx.x - GEMM_BLOCKS) * 256 + threadIdx.x) * 4;
        if (base < EE) {
            int4 d4 = *reinterpret_cast<const int4*>(dst + base);
            int4 s4 = *reinterpret_cast<const int4*>(src + base);
            int p0 = atomicAdd(&g_cursor[d4.x], 1);
            int p1 = atomicAdd(&g_cursor[d4.y], 1);
            int p2 = atomicAdd(&g_cursor[d4.z], 1);
            int p3 = atomicAdd(&g_cursor[d4.w], 1);
            g_csrc[p0] = s4.x;
            g_csrc[p1] = s4.y;
            g_csrc[p2] = s4.z;
            g_csrc[p3] = s4.w;
        }
        return;
    }

    // ---- gemm part ----
    const int t = threadIdx.x;
    const int row0 = blockIdx.x * GR;
    const int rg = t >> 2;
    const int c0 = (t & 3) * 4;

    auto issue_tile = [&](int tile, int buf) {
        int k0 = tile * KT;
        #pragma unroll
        for (int j = 0; j < 4; j++) {
            int q = t + j * 256;
            int r = q >> 2;
            int cq = (q & 3) * 4;
            int grow = row0 + r;
            unsigned int sa = (unsigned int)__cvta_generic_to_shared(&xs[buf][r][cq]);
            CP_ASYNC16(sa, x + (size_t)grow * F_IN + k0 + cq, grow < NN);
        }
        if (t < 64) {
            int r = t >> 2;
            int cq = (t & 3) * 4;
            unsigned int sa = (unsigned int)__cvta_generic_to_shared(&ws[buf][r][cq]);
            CP_ASYNC16(sa, W1 + (size_t)(k0 + r) * HH + cq, 1);
        }
    };

    float acc[4][4] = {};

    issue_tile(0, 0);
    CP_COMMIT();

    #pragma unroll 4
    for (int it = 0; it < NTILES; it++) {
        int buf = it & 1;
        if (it + 1 < NTILES) {
            issue_tile(it + 1, buf ^ 1);
            CP_COMMIT();
            CP_WAIT(1);
        } else {
            CP_WAIT(0);
        }
        __syncthreads();

        #pragma unroll
        for (int kk = 0; kk < KT; kk++) {
            float4 w = *reinterpret_cast<const float4*>(&ws[buf][kk][c0]);
            #pragma unroll
            for (int i = 0; i < 4; i++) {
                float xv = xs[buf][rg + 64 * i][kk];
                acc[i][0] = fmaf(xv, w.x, acc[i][0]);
                acc[i][1] = fmaf(xv, w.y, acc[i][1]);
                acc[i][2] = fmaf(xv, w.z, acc[i][2]);
                acc[i][3] = fmaf(xv, w.w, acc[i][3]);
            }
        }
        __syncthreads();
    }

    #pragma unroll
    for (int i = 0; i < 4; i++) {
        int row = row0 + rg + 64 * i;
        if (row < NN) {
            float4 h = make_float4(acc[i][0], acc[i][1], acc[i][2], acc[i][3]);
            *reinterpret_cast<float4*>(g_h1 + (size_t)row * HH + c0) = h;
        }
    }
}

// ---------------------------------------------------------------------------
// Fused: layer-1 CSR gather + relu + bias + (h2 @ W2) -> t2. 4 threads/node.
__global__ void __launch_bounds__(256) k_gather1_t2(const float* __restrict__ b1,
                                                    const float* __restrict__ W2) {
    __shared__ float w2s[HH][CPAD];
    __shared__ float b1s[HH];
    if (threadIdx.x < HH * CC) {
        int k = threadIdx.x / CC, c = threadIdx.x % CC;
        w2s[k][c] = W2[threadIdx.x];
    }
    if (threadIdx.x < HH) {
        b1s[threadIdx.x] = b1[threadIdx.x];
        w2s[threadIdx.x][CC] = 0.0f;
    }
    __syncthreads();

    int tid = blockIdx.x * blockDim.x + threadIdx.x;
    int iraw = tid >> 2;
    bool valid = iraw < NN;
    int i = valid ? iraw : NN - 1;   // clamp: keep warp converged for shfl
    int p = tid & 3;

    int beg = g_rowptr[i];
    int end = g_rowptr[i + 1];
    float di = g_dinv[i];

    float4 self = *reinterpret_cast<const float4*>(g_h1 + (size_t)i * HH + p * 4);
    float4 acc = make_float4(di * self.x, di * self.y, di * self.z, di * self.w);

    int j = beg;
    for (; j + 3 < end; j += 4) {
        int s0 = g_csrc[j];
        int s1 = g_csrc[j + 1];
        int s2 = g_csrc[j + 2];
        int s3 = g_csrc[j + 3];
        float w0 = g_dinv[s0], w1 = g_dinv[s1], w2 = g_dinv[s2], w3 = g_dinv[s3];
        float4 v0 = *reinterpret_cast<const float4*>(g_h1 + (size_t)s0 * HH + p * 4);
        float4 v1 = *reinterpret_cast<const float4*>(g_h1 + (size_t)s1 * HH + p * 4);
        float4 v2 = *reinterpret_cast<const float4*>(g_h1 + (size_t)s2 * HH + p * 4);
        float4 v3 = *reinterpret_cast<const float4*>(g_h1 + (size_t)s3 * HH + p * 4);
        acc.x = fmaf(w0, v0.x, acc.x); acc.y = fmaf(w0, v0.y, acc.y);
        acc.z = fmaf(w0, v0.z, acc.z); acc.w = fmaf(w0, v0.w, acc.w);
        acc.x = fmaf(w1, v1.x, acc.x); acc.y = fmaf(w1, v1.y, acc.y);
        acc.z = fmaf(w1, v1.z, acc.z); acc.w = fmaf(w1, v1.w, acc.w);
        acc.x = fmaf(w2, v2.x, acc.x); acc.y = fmaf(w2, v2.y, acc.y);
        acc.z = fmaf(w2, v2.z, acc.z); acc.w = fmaf(w2, v2.w, acc.w);
        acc.x = fmaf(w3, v3.x, acc.x); acc.y = fmaf(w3, v3.y, acc.y);
        acc.z = fmaf(w3, v3.z, acc.z); acc.w = fmaf(w3, v3.w, acc.w);
    }
    for (; j < end; j++) {
        int s0 = g_csrc[j];
        float w0 = g_dinv[s0];
        float4 v0 = *reinterpret_cast<const float4*>(g_h1 + (size_t)s0 * HH + p * 4);
        acc.x = fmaf(w0, v0.x, acc.x); acc.y = fmaf(w0, v0.y, acc.y);
        acc.z = fmaf(w0, v0.z, acc.z); acc.w = fmaf(w0, v0.w, acc.w);
    }

    // out1 slice + bias + relu (slice p covers k = 4p..4p+3)
    float4 hh;
    hh.x = fmaxf(di * acc.x + b1s[p * 4 + 0], 0.0f);
    hh.y = fmaxf(di * acc.y + b1s[p * 4 + 1], 0.0f);
    hh.z = fmaxf(di * acc.z + b1s[p * 4 + 2], 0.0f);
    hh.w = fmaxf(di * acc.w + b1s[p * 4 + 3], 0.0f);

    // butterfly: gather all 4 slices of this node into canonical order
    const unsigned FULL = 0xFFFFFFFFu;
    float4 o1;
    o1.x = __shfl_xor_sync(FULL, hh.x, 1);
    o1.y = __shfl_xor_sync(FULL, hh.y, 1);
    o1.z = __shfl_xor_sync(FULL, hh.z, 1);
    o1.w = __shfl_xor_sync(FULL, hh.w, 1);
    bool low1 = (p & 1) == 0;
    float4 a = low1 ? hh : o1;
    float4 b = low1 ? o1 : hh;

    float4 pa, pb;
    pa.x = __shfl_xor_sync(FULL, a.x, 2);
    pa.y = __shfl_xor_sync(FULL, a.y, 2);
    pa.z = __shfl_xor_sync(FULL, a.z, 2);
    pa.w = __shfl_xor_sync(FULL, a.w, 2);
    pb.x = __shfl_xor_sync(FULL, b.x, 2);
    pb.y = __shfl_xor_sync(FULL, b.y, 2);
    pb.z = __shfl_xor_sync(FULL, b.z, 2);
    pb.w = __shfl_xor_sync(FULL, b.w, 2);
    bool low2 = (p & 2) == 0;
    float4 s0 = low2 ? a : pa;
    float4 s1 = low2 ? b : pb;
    float4 s2 = low2 ? pa : a;
    float4 s3 = low2 ? pb : b;

    float h[HH] = { s0.x, s0.y, s0.z, s0.w, s1.x, s1.y, s1.z, s1.w,
                    s2.x, s2.y, s2.z, s2.w, s3.x, s3.y, s3.z, s3.w };

    int c0 = p * 2;
    float r0 = 0.0f, r1 = 0.0f;
    #pragma unroll
    for (int k = 0; k < HH; k++) {
        r0 = fmaf(h[k], w2s[k][c0], r0);
        r1 = fmaf(h[k], w2s[k][c0 + 1], r1);
    }
    if (valid) {
        float2 r = make_float2(r0, r1);
        *reinterpret_cast<float2*>(g_t2 + (size_t)i * CPAD + c0) = r;
    }
}

// ---------------------------------------------------------------------------
// Layer-2 aggregation + bias + log_softmax, fused. 2 threads per node.
// Also re-zeroes g_cnt for the next invocation.
__global__ void __launch_bounds__(256) k_gather2_fin(const float* __restrict__ b2,
                                                     float* __restrict__ out) {
    int tid = blockIdx.x * blockDim.x + threadIdx.x;
    if (tid < NN) g_cnt[tid] = 0;    // reset for next call (grid covers 2*NN >= NN)

    int iraw = tid >> 1;
    bool valid = iraw < NN;
    int i = valid ? iraw : NN - 1;   // clamp: keep full warp for shfl
    int p = tid & 1;

    int beg = g_rowptr[i];
    int end = g_rowptr[i + 1];
    float di = g_dinv[i];

    float4 self = *reinterpret_cast<const float4*>(g_t2 + (size_t)i * CPAD + p * 4);
    float4 acc = make_float4(di * self.x, di * self.y, di * self.z, di * self.w);

    int j = beg;
    for (; j + 3 < end; j += 4) {
        int s0 = g_csrc[j];
        int s1 = g_csrc[j + 1];
        int s2 = g_csrc[j + 2];
        int s3 = g_csrc[j + 3];
        float w0 = g_dinv[s0], w1 = g_dinv[s1], w2 = g_dinv[s2], w3 = g_dinv[s3];
        float4 v0 = *reinterpret_cast<const float4*>(g_t2 + (size_t)s0 * CPAD + p * 4);
        float4 v1 = *reinterpret_cast<const float4*>(g_t2 + (size_t)s1 * CPAD + p * 4);
        float4 v2 = *reinterpret_cast<const float4*>(g_t2 + (size_t)s2 * CPAD + p * 4);
        float4 v3 = *reinterpret_cast<const float4*>(g_t2 + (size_t)s3 * CPAD + p * 4);
        acc.x = fmaf(w0, v0.x, acc.x); acc.y = fmaf(w0, v0.y, acc.y);
        acc.z = fmaf(w0, v0.z, acc.z); acc.w = fmaf(w0, v0.w, acc.w);
        acc.x = fmaf(w1, v1.x, acc.x); acc.y = fmaf(w1, v1.y, acc.y);
        acc.z = fmaf(w1, v1.z, acc.z); acc.w = fmaf(w1, v1.w, acc.w);
        acc.x = fmaf(w2, v2.x, acc.x); acc.y = fmaf(w2, v2.y, acc.y);
        acc.z = fmaf(w2, v2.z, acc.z); acc.w = fmaf(w2, v2.w, acc.w);
        acc.x = fmaf(w3, v3.x, acc.x); acc.y = fmaf(w3, v3.y, acc.y);
        acc.z = fmaf(w3, v3.z, acc.z); acc.w = fmaf(w3, v3.w, acc.w);
    }
    for (; j < end; j++) {
        int s0 = g_csrc[j];
        float w0 = g_dinv[s0];
        float4 v0 = *reinterpret_cast<const float4*>(g_t2 + (size_t)s0 * CPAD + p * 4);
        acc.x = fmaf(w0, v0.x, acc.x); acc.y = fmaf(w0, v0.y, acc.y);
        acc.z = fmaf(w0, v0.z, acc.z); acc.w = fmaf(w0, v0.w, acc.w);
    }

    // logits for this thread's 4 class slots (slot 7 = padding -> -inf)
    float val[4];
    val[0] = di * acc.x; val[1] = di * acc.y; val[2] = di * acc.z; val[3] = di * acc.w;
    #pragma unroll
    for (int k = 0; k < 4; k++) {
        int c = p * 4 + k;
        val[k] = (c < CC) ? val[k] + b2[c] : -1e30f;
    }

    float m4 = fmaxf(fmaxf(val[0], val[1]), fmaxf(val[2], val[3]));
    float mo = __shfl_xor_sync(0xFFFFFFFFu, m4, 1);
    float m = fmaxf(m4, mo);

    float s4 = __expf(val[0] - m) + __expf(val[1] - m) +
               __expf(val[2] - m) + __expf(val[3] - m);
    float so = __shfl_xor_sync(0xFFFFFFFFu, s4, 1);
    float lse = m + __logf(s4 + so);

    if (valid) {
        #pragma unroll
        for (int k = 0; k < 4; k++) {
            int c = p * 4 + k;
            if (c < CC) out[(size_t)i * CC + c] = val[k] - lse;
        }
    }
}

// ---------------------------------------------------------------------------
extern "C" void kernel_launch(void* const* d_in, const int* in_sizes, int n_in,
                              void* d_out, int out_size) {
    const float* x    = (const float*)d_in[0];
    const int* eidx   = (const int*)d_in[1];
    const float* W1   = (const float*)d_in[2];
    const float* b1   = (const float*)d_in[3];
    const float* W2   = (const float*)d_in[4];
    const float* b2   = (const float*)d_in[5];
    float* out        = (float*)d_out;

    const int* src = eidx;        // edge_index[0]
    const int* dst = eidx + EE;   // edge_index[1]

    const int TB = 256;
    k_hist<<<EDGE_BLOCKS, TB>>>(dst);
    k_scan1<<<NSB, SB>>>();
    k_scan3<<<(NN + 255) / 256, 256>>>();
    k_gemm1_permute<<<GEMM_BLOCKS + EDGE_BLOCKS, TB>>>(x, W1, src, dst);
    k_gather1_t2<<<(NN * 4 + TB - 1) / TB, TB>>>(b1, W2);
    k_gather2_fin<<<(NN * 2 + TB - 1) / TB, TB>>>(b2, out);
}